// round 1
// baseline (speedup 1.0000x reference)
#include <cuda_runtime.h>
#include <cuda_bf16.h>
#include <math.h>

// Problem constants
#define NN 50000
#define EE 800000
#define FF 86
#define HH 128
#define EDD 16
#define CC 18
#define GG 64
#define NEG_SLOPE 0.2f

// ---------------- scratch (static device globals; no allocation) ----------------
__device__ int   d_deg[NN];
__device__ int   d_cur[NN];
__device__ int   d_off[NN + 1];
__device__ int   d_srcs[EE];
__device__ float d_ea1[EE];
__device__ float d_ea2[EE];
__device__ float d_aw[EE];
__device__ float d_h[(size_t)NN * HH];   // per-layer transformed features
__device__ float d_o[(size_t)NN * HH];   // per-layer output
__device__ float d_hs[NN];
__device__ float d_hd[NN];
__device__ float d_v1[EDD];
__device__ float d_v2[EDD];
__device__ float d_pool[GG * HH];

// ---------------- kernels ----------------

__global__ void zero_k() {
    int i = blockIdx.x * blockDim.x + threadIdx.x;
    if (i < NN) { d_deg[i] = 0; d_cur[i] = 0; }
    if (i < GG * HH) d_pool[i] = 0.0f;
}

// v1 = We1 @ ae1, v2 = We2 @ ae2  (each [16])
__global__ void precomp_v_k(const float* __restrict__ We1, const float* __restrict__ ae1,
                            const float* __restrict__ We2, const float* __restrict__ ae2) {
    int t = threadIdx.x;
    if (t < EDD) {
        float s = 0.f;
        for (int h = 0; h < HH; h++) s += We1[t * HH + h] * ae1[h];
        d_v1[t] = s;
    } else if (t < 2 * EDD) {
        int k = t - EDD;
        float s = 0.f;
        for (int h = 0; h < HH; h++) s += We2[k * HH + h] * ae2[h];
        d_v2[k] = s;
    }
}

__global__ void hist_k(const int* __restrict__ dst) {
    int e = blockIdx.x * blockDim.x + threadIdx.x;
    if (e < EE) atomicAdd(&d_deg[dst[e]], 1);
}

// single-block exclusive scan of d_deg -> d_off (N=50000)
__global__ void scan_k() {
    __shared__ int sh[1024];
    __shared__ int carry_s;
    int tid = threadIdx.x;
    if (tid == 0) carry_s = 0;
    __syncthreads();
    for (int base = 0; base < NN; base += 1024) {
        int i = base + tid;
        int v = (i < NN) ? d_deg[i] : 0;
        sh[tid] = v;
        __syncthreads();
        int c0 = carry_s;
        for (int ofs = 1; ofs < 1024; ofs <<= 1) {
            int t = (tid >= ofs) ? sh[tid - ofs] : 0;
            __syncthreads();
            sh[tid] += t;
            __syncthreads();
        }
        if (i < NN) d_off[i] = c0 + sh[tid] - v;   // exclusive
        __syncthreads();
        if (tid == 1023) carry_s = c0 + sh[1023];
        __syncthreads();
    }
    if (tid == 0) d_off[NN] = carry_s;
}

// scatter edges into CSR-by-dst; also compute per-edge scalars for both layers
__global__ void scatter_k(const int* __restrict__ src, const int* __restrict__ dst,
                          const float* __restrict__ edge_attr) {
    int e = blockIdx.x * blockDim.x + threadIdx.x;
    if (e >= EE) return;
    int d = dst[e];
    int p = d_off[d] + atomicAdd(&d_cur[d], 1);
    d_srcs[p] = src[e];
    float s1 = 0.f, s2 = 0.f;
    const float* ea = edge_attr + (size_t)e * EDD;
#pragma unroll
    for (int k = 0; k < EDD; k++) {
        float x = ea[k];
        s1 += x * d_v1[k];
        s2 += x * d_v2[k];
    }
    d_ea1[p] = s1;
    d_ea2[p] = s2;
}

// C[M,128] = A[M,K] @ B[K,128], fp32, 128x128x8 tiles, 256 threads, 8x8 microtile
__global__ __launch_bounds__(256) void sgemm_k(const float* __restrict__ A,
                                               const float* __restrict__ B,
                                               float* __restrict__ C,
                                               int M, int K) {
    __shared__ float As[8][128];
    __shared__ float Bs[8][128];
    int tid = threadIdx.x;
    int tx = tid & 15, ty = tid >> 4;
    int rowBase = blockIdx.x * 128;
    float acc[8][8];
#pragma unroll
    for (int i = 0; i < 8; i++)
#pragma unroll
        for (int j = 0; j < 8; j++) acc[i][j] = 0.f;

    int ar = tid >> 1, ac0 = (tid & 1) * 4;
    int br = tid >> 5, bc = (tid & 31) * 4;

    for (int k0 = 0; k0 < K; k0 += 8) {
        int arow = rowBase + ar;
#pragma unroll
        for (int i = 0; i < 4; i++) {
            int kk = k0 + ac0 + i;
            As[ac0 + i][ar] = (arow < M && kk < K) ? A[(size_t)arow * K + kk] : 0.f;
        }
        {
            int kk = k0 + br;
            float4 bv = make_float4(0.f, 0.f, 0.f, 0.f);
            if (kk < K) bv = *(const float4*)&B[(size_t)kk * HH + bc];
            *(float4*)&Bs[br][bc] = bv;
        }
        __syncthreads();
#pragma unroll
        for (int k = 0; k < 8; k++) {
            float a[8], b[8];
#pragma unroll
            for (int i = 0; i < 8; i++) a[i] = As[k][ty * 8 + i];
#pragma unroll
            for (int j = 0; j < 8; j++) b[j] = Bs[k][tx * 8 + j];
#pragma unroll
            for (int i = 0; i < 8; i++)
#pragma unroll
                for (int j = 0; j < 8; j++)
                    acc[i][j] = fmaf(a[i], b[j], acc[i][j]);
        }
        __syncthreads();
    }
#pragma unroll
    for (int i = 0; i < 8; i++) {
        int r = rowBase + ty * 8 + i;
        if (r < M) {
            float4 v0 = make_float4(acc[i][0], acc[i][1], acc[i][2], acc[i][3]);
            float4 v1 = make_float4(acc[i][4], acc[i][5], acc[i][6], acc[i][7]);
            *(float4*)&C[(size_t)r * HH + tx * 8] = v0;
            *(float4*)&C[(size_t)r * HH + tx * 8 + 4] = v1;
        }
    }
}

// hs[n] = h[n,:]·a_src ; hd[n] = h[n,:]·a_dst  (warp per node)
__global__ void hsd_k(const float* __restrict__ as, const float* __restrict__ ad) {
    int gt = blockIdx.x * blockDim.x + threadIdx.x;
    int n = gt >> 5, lane = gt & 31;
    if (n >= NN) return;
    const float* hr = d_h + (size_t)n * HH;
    float s = 0.f, d = 0.f;
#pragma unroll
    for (int f = lane; f < HH; f += 32) {
        float hv = hr[f];
        s += hv * as[f];
        d += hv * ad[f];
    }
#pragma unroll
    for (int o = 16; o; o >>= 1) {
        s += __shfl_xor_sync(0xffffffffu, s, o);
        d += __shfl_xor_sync(0xffffffffu, d, o);
    }
    if (lane == 0) { d_hs[n] = s; d_hd[n] = d; }
}

// one warp per dst node: leaky-relu logits -> segment softmax -> weighted gather of h[src]
// out[n,:] = relu( sum_j w_j * h[src_j,:] + bias )
__global__ void attn_agg_k(const float* __restrict__ ea, const float* __restrict__ bias,
                           float* __restrict__ out) {
    int gt = blockIdx.x * blockDim.x + threadIdx.x;
    int n = gt >> 5, lane = gt & 31;
    if (n >= NN) return;
    int b0 = d_off[n], b1 = d_off[n + 1];
    float hdn = d_hd[n];

    // pass 1: logits + max
    float lm = -1e30f;
    for (int j = b0 + lane; j < b1; j += 32) {
        float a = d_hs[d_srcs[j]] + hdn + ea[j];
        a = (a > 0.f) ? a : NEG_SLOPE * a;
        d_aw[j] = a;
        lm = fmaxf(lm, a);
    }
#pragma unroll
    for (int o = 16; o; o >>= 1) lm = fmaxf(lm, __shfl_xor_sync(0xffffffffu, lm, o));

    // pass 1b: exp + sum (each lane touches only its own writes)
    float ls = 0.f;
    for (int j = b0 + lane; j < b1; j += 32) {
        float ex = __expf(d_aw[j] - lm);
        d_aw[j] = ex;
        ls += ex;
    }
#pragma unroll
    for (int o = 16; o; o >>= 1) ls += __shfl_xor_sync(0xffffffffu, ls, o);
    float inv = 1.f / fmaxf(ls, 1e-16f);

    __syncwarp();  // make cross-lane d_aw writes visible

    // pass 2: weighted feature gather; lane handles 4 contiguous features
    float4 acc = make_float4(0.f, 0.f, 0.f, 0.f);
    int fo = lane << 2;
#pragma unroll 4
    for (int j = b0; j < b1; j++) {
        float w = d_aw[j] * inv;
        int s = d_srcs[j];
        float4 hv = *(const float4*)(d_h + (size_t)s * HH + fo);
        acc.x += w * hv.x; acc.y += w * hv.y; acc.z += w * hv.z; acc.w += w * hv.w;
    }
    float4 bv = *(const float4*)(bias + fo);
    float4 o4;
    o4.x = fmaxf(acc.x + bv.x, 0.f);
    o4.y = fmaxf(acc.y + bv.y, 0.f);
    o4.z = fmaxf(acc.z + bv.z, 0.f);
    o4.w = fmaxf(acc.w + bv.w, 0.f);
    *(float4*)(out + (size_t)n * HH + fo) = o4;
}

// global max pool over sorted batch segments (values >= 0 after relu, pool pre-zeroed)
#define NPB 256
__global__ void pool_k(const float* __restrict__ o, const int* __restrict__ batch) {
    int f = threadIdx.x;  // 128
    int n0 = blockIdx.x * NPB;
    int n1 = min(n0 + NPB, NN);
    if (n0 >= NN) return;
    int cur = batch[n0];
    float lm = 0.f;
    for (int n = n0; n < n1; n++) {
        int g = batch[n];
        if (g != cur) {
            atomicMax((int*)&d_pool[cur * HH + f], __float_as_int(lm));
            cur = g;
            lm = 0.f;
        }
        lm = fmaxf(lm, o[(size_t)n * HH + f]);
    }
    atomicMax((int*)&d_pool[cur * HH + f], __float_as_int(lm));
}

// classifier + log_softmax: one warp per graph
__global__ void head_k(const float* __restrict__ Wl, const float* __restrict__ bl,
                       float* __restrict__ out) {
    int g = blockIdx.x;
    int lane = threadIdx.x;
    float logit = -INFINITY;
    if (lane < CC) {
        float s = bl[lane];
        const float* pr = d_pool + g * HH;
        for (int k = 0; k < HH; k++) s += pr[k] * Wl[k * CC + lane];
        logit = s;
    }
    float m = logit;
#pragma unroll
    for (int o = 16; o; o >>= 1) m = fmaxf(m, __shfl_xor_sync(0xffffffffu, m, o));
    float e = (lane < CC) ? __expf(logit - m) : 0.f;
    float se = e;
#pragma unroll
    for (int o = 16; o; o >>= 1) se += __shfl_xor_sync(0xffffffffu, se, o);
    float lse = m + logf(se);
    if (lane < CC) out[g * CC + lane] = logit - lse;
}

// ---------------- launch ----------------
extern "C" void kernel_launch(void* const* d_in, const int* in_sizes, int n_in,
                              void* d_out, int out_size) {
    const float* x         = (const float*)d_in[0];
    const int*   eidx      = (const int*)d_in[1];
    const float* edge_attr = (const float*)d_in[2];
    const int*   batch     = (const int*)d_in[3];
    const float* W1  = (const float*)d_in[4];
    const float* We1 = (const float*)d_in[5];
    const float* as1 = (const float*)d_in[6];
    const float* ad1 = (const float*)d_in[7];
    const float* ae1 = (const float*)d_in[8];
    const float* b1  = (const float*)d_in[9];
    const float* W2  = (const float*)d_in[10];
    const float* We2 = (const float*)d_in[11];
    const float* as2 = (const float*)d_in[12];
    const float* ad2 = (const float*)d_in[13];
    const float* ae2 = (const float*)d_in[14];
    const float* b2  = (const float*)d_in[15];
    const float* Wl  = (const float*)d_in[16];
    const float* bl  = (const float*)d_in[17];
    float* out = (float*)d_out;

    const int* srcp = eidx;
    const int* dstp = eidx + EE;

    float* hbuf; cudaGetSymbolAddress((void**)&hbuf, d_h);
    float* obuf; cudaGetSymbolAddress((void**)&obuf, d_o);
    float* ea1b; cudaGetSymbolAddress((void**)&ea1b, d_ea1);
    float* ea2b; cudaGetSymbolAddress((void**)&ea2b, d_ea2);

    // ---- CSR build + per-edge scalars ----
    zero_k<<<(NN + 255) / 256, 256>>>();
    precomp_v_k<<<1, 64>>>(We1, ae1, We2, ae2);
    hist_k<<<(EE + 255) / 256, 256>>>(dstp);
    scan_k<<<1, 1024>>>();
    scatter_k<<<(EE + 255) / 256, 256>>>(srcp, dstp, edge_attr);

    const int warps_grid = (NN * 32 + 255) / 256;

    // ---- layer 1 ----
    sgemm_k<<<(NN + 127) / 128, 256>>>(x, W1, hbuf, NN, FF);
    hsd_k<<<warps_grid, 256>>>(as1, ad1);
    attn_agg_k<<<warps_grid, 256>>>(ea1b, b1, obuf);

    // ---- layer 2 ----
    sgemm_k<<<(NN + 127) / 128, 256>>>(obuf, W2, hbuf, NN, HH);
    hsd_k<<<warps_grid, 256>>>(as2, ad2);
    attn_agg_k<<<warps_grid, 256>>>(ea2b, b2, obuf);

    // ---- pool + head ----
    pool_k<<<(NN + NPB - 1) / NPB, 128>>>(obuf, batch);
    head_k<<<GG, 32>>>(Wl, bl, out);
}

// round 2
// speedup vs baseline: 1.5520x; 1.5520x over previous
#include <cuda_runtime.h>
#include <cuda_bf16.h>
#include <math.h>
#include <stdint.h>

// Problem constants
#define NN 50000
#define EE 800000
#define FF 86
#define HH 128
#define EDD 16
#define CC 18
#define GG 64
#define NEG_SLOPE 0.2f

#define NBLK ((NN + 255) / 256)   // 196 scan blocks

// ---------------- scratch (static device globals; no allocation) ----------------
__device__ int   d_deg[NN];
__device__ int   d_cur[NN];
__device__ int   d_off[NN + 1];
__device__ int   d_bsum[256];
__device__ int   d_srcs[EE];
__device__ float d_ea1[EE];
__device__ float d_ea2[EE];
__device__ float d_aw[EE];
__device__ float d_h[(size_t)NN * HH];   // per-layer transformed features
__device__ float d_o[(size_t)NN * HH];   // per-layer output
__device__ float d_hs[NN];
__device__ float d_hd[NN];
__device__ float d_v1[EDD];
__device__ float d_v2[EDD];
__device__ float d_pool[GG * HH];

// ---------------- small helpers ----------------
__device__ __forceinline__ float to_tf32(float x) {
    uint32_t u;
    asm("cvt.rna.tf32.f32 %0, %1;" : "=r"(u) : "f"(x));
    return __uint_as_float(u);
}

__device__ __forceinline__ int warp_iscan(int x, int lane) {
#pragma unroll
    for (int o = 1; o < 32; o <<= 1) {
        int y = __shfl_up_sync(0xffffffffu, x, o);
        if (lane >= o) x += y;
    }
    return x;
}

// ---------------- kernels ----------------

__global__ void zero_k() {
    int i = blockIdx.x * blockDim.x + threadIdx.x;
    if (i < NN) { d_deg[i] = 0; d_cur[i] = 0; }
    if (i < GG * HH) d_pool[i] = 0.0f;
}

// v1 = We1 @ ae1, v2 = We2 @ ae2  (each [16])
__global__ void precomp_v_k(const float* __restrict__ We1, const float* __restrict__ ae1,
                            const float* __restrict__ We2, const float* __restrict__ ae2) {
    int t = threadIdx.x;
    if (t < EDD) {
        float s = 0.f;
        for (int h = 0; h < HH; h++) s += We1[t * HH + h] * ae1[h];
        d_v1[t] = s;
    } else if (t < 2 * EDD) {
        int k = t - EDD;
        float s = 0.f;
        for (int h = 0; h < HH; h++) s += We2[k * HH + h] * ae2[h];
        d_v2[k] = s;
    }
}

__global__ void hist_k(const int* __restrict__ dst) {
    int e = blockIdx.x * blockDim.x + threadIdx.x;
    if (e < EE) atomicAdd(&d_deg[dst[e]], 1);
}

// ---- 3-phase multi-block exclusive scan of d_deg -> d_off ----
__global__ void scan1_k() {
    __shared__ int ws[8];
    int t = threadIdx.x, lane = t & 31, warp = t >> 5;
    int i = blockIdx.x * 256 + t;
    int v = (i < NN) ? d_deg[i] : 0;
    int wi = warp_iscan(v, lane);
    if (lane == 31) ws[warp] = wi;
    __syncthreads();
    if (warp == 0) {
        int s = (lane < 8) ? ws[lane] : 0;
        int si = warp_iscan(s, lane);
        if (lane < 8) ws[lane] = si - s;  // exclusive
    }
    __syncthreads();
    int excl = ws[warp] + wi - v;
    if (i < NN) d_off[i] = excl;
    if (t == 255) d_bsum[blockIdx.x] = ws[7] + wi;  // block total
}

__global__ void scan2_k() {
    __shared__ int ws[8];
    int t = threadIdx.x, lane = t & 31, warp = t >> 5;
    int v = (t < NBLK) ? d_bsum[t] : 0;
    int wi = warp_iscan(v, lane);
    if (lane == 31) ws[warp] = wi;
    __syncthreads();
    if (warp == 0) {
        int s = (lane < 8) ? ws[lane] : 0;
        int si = warp_iscan(s, lane);
        if (lane < 8) ws[lane] = si - s;
    }
    __syncthreads();
    int incl = ws[warp] + wi;
    if (t < NBLK) d_bsum[t] = incl - v;   // exclusive
    if (t == NBLK - 1) d_off[NN] = incl;  // grand total (== EE)
}

__global__ void scan3_k() {
    int i = blockIdx.x * 256 + threadIdx.x;
    if (i < NN) d_off[i] += d_bsum[blockIdx.x];
}

// scatter edges into CSR-by-dst; also compute per-edge scalars for both layers
__global__ void scatter_k(const int* __restrict__ src, const int* __restrict__ dst,
                          const float* __restrict__ edge_attr) {
    int e = blockIdx.x * blockDim.x + threadIdx.x;
    if (e >= EE) return;
    int d = dst[e];
    int p = d_off[d] + atomicAdd(&d_cur[d], 1);
    d_srcs[p] = src[e];
    float s1 = 0.f, s2 = 0.f;
    const float* ea = edge_attr + (size_t)e * EDD;
#pragma unroll
    for (int k = 0; k < EDD; k++) {
        float x = ea[k];
        s1 += x * d_v1[k];
        s2 += x * d_v2[k];
    }
    d_ea1[p] = s1;
    d_ea2[p] = s2;
}

// ---------------- tf32 tensor-core GEMM: C[M,128] = A[M,K] @ B[K,128] ----------------
// block tile 128x128, K chunked by 32; 8 warps, warp tile 64x32 (m16n8k8 atoms)
#define KC 32
__global__ __launch_bounds__(256) void gemm_tf32_k(const float* __restrict__ A,
                                                   const float* __restrict__ B,
                                                   float* __restrict__ C,
                                                   int M, int K) {
    __shared__ float As[128][KC + 4];    // stride 36: conflict-free A frag loads
    __shared__ float Bs[KC][HH + 4];     // stride 132
    int tid = threadIdx.x;
    int wid = tid >> 5, lane = tid & 31;
    int mw = wid >> 2, nw = wid & 3;          // 2 x 4 warp grid
    int gp = lane >> 2, t4 = lane & 3;        // fragment coords
    int rowBase = blockIdx.x * 128;

    float acc[4][4][4];
#pragma unroll
    for (int a = 0; a < 4; a++)
#pragma unroll
        for (int b = 0; b < 4; b++)
#pragma unroll
            for (int c = 0; c < 4; c++) acc[a][b][c] = 0.f;

    int nChunks = (K + KC - 1) / KC;
    for (int kc = 0; kc < nChunks; kc++) {
        int kbase = kc * KC;
        // load A chunk: 128 rows x 32 k, scalar loads (K may be 86: unaligned rows)
        {
            int rl = tid >> 3;   // 0..31
            int kl = tid & 7;    // 0..7
#pragma unroll
            for (int i = 0; i < 4; i++) {
                int r = rl + i * 32;
                int grow = rowBase + r;
                const float* arow = A + (size_t)grow * K;
#pragma unroll
                for (int j = 0; j < 4; j++) {
                    int k = kl + j * 8;
                    int gk = kbase + k;
                    float v = (grow < M && gk < K) ? arow[gk] : 0.f;
                    As[r][k] = to_tf32(v);
                }
            }
        }
        // load B chunk: 32 k x 128 n, float4 loads
        {
#pragma unroll
            for (int i = 0; i < 4; i++) {
                int idx = tid + 256 * i;
                int k = idx >> 5, f4 = idx & 31;
                int gk = kbase + k;
                float4 bv = make_float4(0.f, 0.f, 0.f, 0.f);
                if (gk < K) bv = *(const float4*)&B[(size_t)gk * HH + f4 * 4];
                Bs[k][f4 * 4 + 0] = to_tf32(bv.x);
                Bs[k][f4 * 4 + 1] = to_tf32(bv.y);
                Bs[k][f4 * 4 + 2] = to_tf32(bv.z);
                Bs[k][f4 * 4 + 3] = to_tf32(bv.w);
            }
        }
        __syncthreads();
#pragma unroll
        for (int ka = 0; ka < 4; ka++) {
            int kb = ka * 8;
            uint32_t af[4][4];
#pragma unroll
            for (int mi = 0; mi < 4; mi++) {
                int r0 = mw * 64 + mi * 16 + gp;
                af[mi][0] = __float_as_uint(As[r0][kb + t4]);
                af[mi][1] = __float_as_uint(As[r0 + 8][kb + t4]);
                af[mi][2] = __float_as_uint(As[r0][kb + t4 + 4]);
                af[mi][3] = __float_as_uint(As[r0 + 8][kb + t4 + 4]);
            }
            uint32_t bf[4][2];
#pragma unroll
            for (int ni = 0; ni < 4; ni++) {
                int c0 = nw * 32 + ni * 8 + gp;
                bf[ni][0] = __float_as_uint(Bs[kb + t4][c0]);
                bf[ni][1] = __float_as_uint(Bs[kb + t4 + 4][c0]);
            }
#pragma unroll
            for (int mi = 0; mi < 4; mi++)
#pragma unroll
                for (int ni = 0; ni < 4; ni++) {
                    asm volatile(
                        "mma.sync.aligned.m16n8k8.row.col.f32.tf32.tf32.f32 "
                        "{%0,%1,%2,%3}, {%4,%5,%6,%7}, {%8,%9}, {%0,%1,%2,%3};"
                        : "+f"(acc[mi][ni][0]), "+f"(acc[mi][ni][1]),
                          "+f"(acc[mi][ni][2]), "+f"(acc[mi][ni][3])
                        : "r"(af[mi][0]), "r"(af[mi][1]), "r"(af[mi][2]), "r"(af[mi][3]),
                          "r"(bf[ni][0]), "r"(bf[ni][1]));
                }
        }
        __syncthreads();
    }
    // epilogue
#pragma unroll
    for (int mi = 0; mi < 4; mi++) {
        int r0 = rowBase + mw * 64 + mi * 16 + gp;
#pragma unroll
        for (int ni = 0; ni < 4; ni++) {
            int c = nw * 32 + ni * 8 + 2 * t4;
            if (r0 < M) {
                C[(size_t)r0 * HH + c]     = acc[mi][ni][0];
                C[(size_t)r0 * HH + c + 1] = acc[mi][ni][1];
            }
            if (r0 + 8 < M) {
                C[(size_t)(r0 + 8) * HH + c]     = acc[mi][ni][2];
                C[(size_t)(r0 + 8) * HH + c + 1] = acc[mi][ni][3];
            }
        }
    }
}

// hs[n] = h[n,:]·a_src ; hd[n] = h[n,:]·a_dst  (warp per node)
__global__ void hsd_k(const float* __restrict__ as, const float* __restrict__ ad) {
    int gt = blockIdx.x * blockDim.x + threadIdx.x;
    int n = gt >> 5, lane = gt & 31;
    if (n >= NN) return;
    const float* hr = d_h + (size_t)n * HH;
    float s = 0.f, d = 0.f;
#pragma unroll
    for (int f = lane; f < HH; f += 32) {
        float hv = hr[f];
        s += hv * as[f];
        d += hv * ad[f];
    }
#pragma unroll
    for (int o = 16; o; o >>= 1) {
        s += __shfl_xor_sync(0xffffffffu, s, o);
        d += __shfl_xor_sync(0xffffffffu, d, o);
    }
    if (lane == 0) { d_hs[n] = s; d_hd[n] = d; }
}

// one warp per dst node: leaky-relu logits -> segment softmax -> weighted gather of h[src]
__global__ void attn_agg_k(const float* __restrict__ ea, const float* __restrict__ bias,
                           float* __restrict__ out) {
    int gt = blockIdx.x * blockDim.x + threadIdx.x;
    int n = gt >> 5, lane = gt & 31;
    if (n >= NN) return;
    int b0 = d_off[n], b1 = d_off[n + 1];
    float hdn = d_hd[n];

    float lm = -1e30f;
    for (int j = b0 + lane; j < b1; j += 32) {
        float a = d_hs[d_srcs[j]] + hdn + ea[j];
        a = (a > 0.f) ? a : NEG_SLOPE * a;
        d_aw[j] = a;
        lm = fmaxf(lm, a);
    }
#pragma unroll
    for (int o = 16; o; o >>= 1) lm = fmaxf(lm, __shfl_xor_sync(0xffffffffu, lm, o));

    float ls = 0.f;
    for (int j = b0 + lane; j < b1; j += 32) {
        float ex = __expf(d_aw[j] - lm);
        d_aw[j] = ex;
        ls += ex;
    }
#pragma unroll
    for (int o = 16; o; o >>= 1) ls += __shfl_xor_sync(0xffffffffu, ls, o);
    float inv = 1.f / fmaxf(ls, 1e-16f);

    __syncwarp();

    float4 acc = make_float4(0.f, 0.f, 0.f, 0.f);
    int fo = lane << 2;
#pragma unroll 4
    for (int j = b0; j < b1; j++) {
        float w = d_aw[j] * inv;
        int s = d_srcs[j];
        float4 hv = *(const float4*)(d_h + (size_t)s * HH + fo);
        acc.x += w * hv.x; acc.y += w * hv.y; acc.z += w * hv.z; acc.w += w * hv.w;
    }
    float4 bv = *(const float4*)(bias + fo);
    float4 o4;
    o4.x = fmaxf(acc.x + bv.x, 0.f);
    o4.y = fmaxf(acc.y + bv.y, 0.f);
    o4.z = fmaxf(acc.z + bv.z, 0.f);
    o4.w = fmaxf(acc.w + bv.w, 0.f);
    *(float4*)(out + (size_t)n * HH + fo) = o4;
}

// global max pool over sorted batch segments (values >= 0 after relu, pool pre-zeroed)
#define NPB 256
__global__ void pool_k(const float* __restrict__ o, const int* __restrict__ batch) {
    int f = threadIdx.x;  // 128
    int n0 = blockIdx.x * NPB;
    int n1 = min(n0 + NPB, NN);
    if (n0 >= NN) return;
    int cur = batch[n0];
    float lm = 0.f;
    for (int n = n0; n < n1; n++) {
        int g = batch[n];
        if (g != cur) {
            atomicMax((int*)&d_pool[cur * HH + f], __float_as_int(lm));
            cur = g;
            lm = 0.f;
        }
        lm = fmaxf(lm, o[(size_t)n * HH + f]);
    }
    atomicMax((int*)&d_pool[cur * HH + f], __float_as_int(lm));
}

// classifier + log_softmax: one warp per graph
__global__ void head_k(const float* __restrict__ Wl, const float* __restrict__ bl,
                       float* __restrict__ out) {
    int g = blockIdx.x;
    int lane = threadIdx.x;
    float logit = -INFINITY;
    if (lane < CC) {
        float s = bl[lane];
        const float* pr = d_pool + g * HH;
        for (int k = 0; k < HH; k++) s += pr[k] * Wl[k * CC + lane];
        logit = s;
    }
    float m = logit;
#pragma unroll
    for (int o = 16; o; o >>= 1) m = fmaxf(m, __shfl_xor_sync(0xffffffffu, m, o));
    float e = (lane < CC) ? __expf(logit - m) : 0.f;
    float se = e;
#pragma unroll
    for (int o = 16; o; o >>= 1) se += __shfl_xor_sync(0xffffffffu, se, o);
    float lse = m + logf(se);
    if (lane < CC) out[g * CC + lane] = logit - lse;
}

// ---------------- launch ----------------
extern "C" void kernel_launch(void* const* d_in, const int* in_sizes, int n_in,
                              void* d_out, int out_size) {
    const float* x         = (const float*)d_in[0];
    const int*   eidx      = (const int*)d_in[1];
    const float* edge_attr = (const float*)d_in[2];
    const int*   batch     = (const int*)d_in[3];
    const float* W1  = (const float*)d_in[4];
    const float* We1 = (const float*)d_in[5];
    const float* as1 = (const float*)d_in[6];
    const float* ad1 = (const float*)d_in[7];
    const float* ae1 = (const float*)d_in[8];
    const float* b1  = (const float*)d_in[9];
    const float* W2  = (const float*)d_in[10];
    const float* We2 = (const float*)d_in[11];
    const float* as2 = (const float*)d_in[12];
    const float* ad2 = (const float*)d_in[13];
    const float* ae2 = (const float*)d_in[14];
    const float* b2  = (const float*)d_in[15];
    const float* Wl  = (const float*)d_in[16];
    const float* bl  = (const float*)d_in[17];
    float* out = (float*)d_out;

    const int* srcp = eidx;
    const int* dstp = eidx + EE;

    float* hbuf; cudaGetSymbolAddress((void**)&hbuf, d_h);
    float* obuf; cudaGetSymbolAddress((void**)&obuf, d_o);
    float* ea1b; cudaGetSymbolAddress((void**)&ea1b, d_ea1);
    float* ea2b; cudaGetSymbolAddress((void**)&ea2b, d_ea2);

    // ---- CSR build + per-edge scalars ----
    zero_k<<<(NN + 255) / 256, 256>>>();
    precomp_v_k<<<1, 64>>>(We1, ae1, We2, ae2);
    hist_k<<<(EE + 255) / 256, 256>>>(dstp);
    scan1_k<<<NBLK, 256>>>();
    scan2_k<<<1, 256>>>();
    scan3_k<<<NBLK, 256>>>();
    scatter_k<<<(EE + 255) / 256, 256>>>(srcp, dstp, edge_attr);

    const int warps_grid = (NN * 32 + 255) / 256;

    // ---- layer 1 ----
    gemm_tf32_k<<<(NN + 127) / 128, 256>>>(x, W1, hbuf, NN, FF);
    hsd_k<<<warps_grid, 256>>>(as1, ad1);
    attn_agg_k<<<warps_grid, 256>>>(ea1b, b1, obuf);

    // ---- layer 2 ----
    gemm_tf32_k<<<(NN + 127) / 128, 256>>>(obuf, W2, hbuf, NN, HH);
    hsd_k<<<warps_grid, 256>>>(as2, ad2);
    attn_agg_k<<<warps_grid, 256>>>(ea2b, b2, obuf);

    // ---- pool + head ----
    pool_k<<<(NN + NPB - 1) / NPB, 128>>>(obuf, batch);
    head_k<<<GG, 32>>>(Wl, bl, out);
}